// round 4
// baseline (speedup 1.0000x reference)
#include <cuda_runtime.h>
#include <math.h>

// QuantumIQPImageEmbedder — rank-4 factorized closed form.
//
// G = Psi Psi^H factorizes per qubit; absorbing the single-qubit Ising phases
// e^{-i a_k z/2} into the kept states and expanding the two boundary
// couplings as sums over the traced boundary qubit values m gives
//   G = W W^H,  W 16x4:  W[i][(m4,m19)] =
//     e^{-iP(i)} * prod_k s'_k[i_k] * sqrt(p4[m4]) e^{-i b3 zm4 zi3/2}
//                                   * sqrt(p19[m19]) e^{-i b19 zm19 zi0/2}
// rho4 = (1/16)(H4 W)(H4 W)^H and every partial trace is a small Gram of
// V = (1/4) H4 W. The 16x16 Gram / WHTs are never materialized.
// 4 warps: warps 0-2 own quantum blocks 0,1,3 end-to-end (syncwarp only);
// 3 block barriers total.

#define INV_SQRT2F 0.7071067811865476f

__device__ __forceinline__ float2 cmul(float2 a, float2 b) {
    return make_float2(a.x*b.x - a.y*b.y, a.x*b.y + a.y*b.x);
}
__device__ __forceinline__ float2 cmulc(float2 a, float2 b) { // a * conj(b)
    return make_float2(a.x*b.x + a.y*b.y, a.y*b.x - a.x*b.y);
}
__device__ __forceinline__ float2 cadd(float2 a, float2 b) {
    return make_float2(a.x + b.x, a.y + b.y);
}

__global__ void __launch_bounds__(128, 1)
iqp_embed_kernel(const float* __restrict__ x,        // (B,16,4,3)
                 const float* __restrict__ pos_w,    // (16,2)
                 const float* __restrict__ l1,       // (20,2)
                 const float* __restrict__ l2,       // (16,2)
                 const float* __restrict__ hw,       // (512,4)
                 const float* __restrict__ hb,       // (512,)
                 float* __restrict__ out)            // (B,512)
{
    const int b    = blockIdx.x;
    const int t    = threadIdx.x;       // 128 threads
    const int wid  = t >> 5;            // warp 0..3
    const int lane = t & 31;

    __shared__ float2 sprime[3][4][2];  // a-phase-absorbed kept states
    __shared__ float  sqp[3][2][2];     // sqrt boundary probs [slot][4/19][m]
    __shared__ float2 Vs[3][16][4];     // V = (1/4) H4 W per slot
    __shared__ float2 rho012[64], rho123[64], rho01[16], rho23[16];
    __shared__ float2 rq0[4], rq3[4];
    __shared__ float  evals[4], rbuf[4];

    // ---------- hoisted independent loads / trig (hidden under phase A) ----
    float4 hwv0 = ((const float4*)hw)[t      ];
    float4 hwv1 = ((const float4*)hw)[t + 128];
    float4 hwv2 = ((const float4*)hw)[t + 256];
    float4 hwv3 = ((const float4*)hw)[t + 384];
    float  hb0 = hb[t], hb1 = hb[t+128], hb2 = hb[t+256], hb3 = hb[t+384];

    // phase-3 trig: warp wid handles expectation value kk = wid
    float c1, s1v, c2, s2v, c3, s3v;
    __sincosf(l2[2*wid],                   &s1v, &c1);
    __sincosf(l2[2*((wid - 1) & 15) + 1],  &s2v, &c2);
    __sincosf(l2[2*wid + 1],               &s3v, &c3);

    // phase-B trig (coupling factors), warps 0-2 only
    float cb0, sb0, cb1, sb1, cb2, sb2, cb3, sb3, cb19, sb19;
    if (wid < 3) {
        __sincosf(0.5f*l1[1],  &sb0,  &cb0);   // b1[0]
        __sincosf(0.5f*l1[3],  &sb1,  &cb1);   // b1[1]
        __sincosf(0.5f*l1[5],  &sb2,  &cb2);   // b1[2]
        __sincosf(0.5f*l1[7],  &sb3,  &cb3);   // b1[3]  (boundary q3-q4)
        __sincosf(0.5f*l1[39], &sb19, &cb19);  // b1[19] (boundary q19-q0)
    }

    // ---------- Phase A: kept states + boundary probs (per warp/slot) -----
    if (wid < 3) {
        const int kb = (wid == 2) ? 3 : wid;
        if (lane < 4) {
            // color qubit `lane` of patch 4*kb
            const float* xp = x + ((size_t)(b*16 + 4*kb)*4 + lane)*3;
            float cx, sx, cy, sy, cz, sz;
            __sincosf(0.5f*xp[0], &sx, &cx);
            __sincosf(0.5f*xp[1], &sy, &cy);
            __sincosf(0.5f*xp[2], &sz, &cz);
            float2 w0 = make_float2(cy*cx,  sy*sx);
            float2 w1 = make_float2(sy*cx, -cy*sx);
            float2 pz = make_float2(cz, -sz);
            w0 = cmul (w0, pz);
            w1 = cmulc(w1, pz);
            float2 s0 = make_float2((w0.x+w1.x)*INV_SQRT2F, (w0.y+w1.y)*INV_SQRT2F);
            float2 s1 = make_float2((w0.x-w1.x)*INV_SQRT2F, (w0.y-w1.y)*INV_SQRT2F);
            float sa, ca;  __sincosf(0.5f*l1[2*lane], &sa, &ca);   // a1[lane]
            sprime[wid][lane][0] = cmul(s0, make_float2(ca, -sa)); // z=+1
            sprime[wid][lane][1] = cmul(s1, make_float2(ca,  sa)); // z=-1
        } else if (lane < 6) {
            // boundary ancillas: q4 = anc of patch 4kb, q19 = anc of patch 4kb+3
            const int p = 4*kb + ((lane == 4) ? 0 : 3);
            float cx, sx, cy, sy;
            __sincosf(0.5f*pos_w[2*p],     &sx, &cx);
            __sincosf(0.5f*pos_w[2*p + 1], &sy, &cy);
            float2 w0 = make_float2(cy*cx,  sy*sx);
            float2 w1 = make_float2(sy*cx, -cy*sx);
            float2 s0 = make_float2((w0.x+w1.x)*INV_SQRT2F, (w0.y+w1.y)*INV_SQRT2F);
            float2 s1 = make_float2((w0.x-w1.x)*INV_SQRT2F, (w0.y-w1.y)*INV_SQRT2F);
            sqp[wid][lane-4][0] = sqrtf(s0.x*s0.x + s0.y*s0.y);
            sqp[wid][lane-4][1] = sqrtf(s1.x*s1.x + s1.y*s1.y);
        }
        __syncwarp();

        // ---------- Phase B: W columns, shuffle-WHT, V to smem ------------
        const int i  = lane & 15;
        const int i0 = (i>>3)&1, i1 = (i>>2)&1, i2 = (i>>1)&1, i3 = i&1;

        float2 u = cmul(cmul(sprime[wid][0][i0], sprime[wid][1][i1]),
                        cmul(sprime[wid][2][i2], sprime[wid][3][i3]));
        // e^{-iP(i)}: sign_k = zi_k * zi_{k+1} (+1 iff bits equal)
        const float g0 = (i0 == i1) ? sb0 : -sb0;
        const float g1 = (i1 == i2) ? sb1 : -sb1;
        const float g2 = (i2 == i3) ? sb2 : -sb2;
        u = cmul(u, make_float2(cb0, -g0));
        u = cmul(u, make_float2(cb1, -g1));
        u = cmul(u, make_float2(cb2, -g2));

        const float zi3 = 1.f - 2.f*i3, zi0 = 1.f - 2.f*i0;
        const float2 g40  = make_float2(sqp[wid][0][0]*cb3,  -sqp[wid][0][0]*zi3*sb3);
        const float2 g41  = make_float2(sqp[wid][0][1]*cb3,   sqp[wid][0][1]*zi3*sb3);
        const float2 g190 = make_float2(sqp[wid][1][0]*cb19, -sqp[wid][1][0]*zi0*sb19);
        const float2 g191 = make_float2(sqp[wid][1][1]*cb19,  sqp[wid][1][1]*zi0*sb19);

        const float2 t0 = cmul(u, g40), t1 = cmul(u, g41);
        float2 w[4];
        w[0] = cmul(t0, g190);  w[1] = cmul(t0, g191);
        w[2] = cmul(t1, g190);  w[3] = cmul(t1, g191);

        // WHT over i (low 4 lane bits), 4 columns
        #pragma unroll
        for (int m = 1; m < 16; m <<= 1) {
            #pragma unroll
            for (int c = 0; c < 4; ++c) {
                const float px = __shfl_xor_sync(0xffffffffu, w[c].x, m);
                const float py = __shfl_xor_sync(0xffffffffu, w[c].y, m);
                if (i & m) { w[c].x = px - w[c].x; w[c].y = py - w[c].y; }
                else       { w[c].x += px;         w[c].y += py;         }
            }
        }
        if (lane < 16) {
            #pragma unroll
            for (int c = 0; c < 4; ++c)
                Vs[wid][i][c] = make_float2(w[c].x*0.25f, w[c].y*0.25f);
        }
        __syncwarp();

        // ---------- Phase C: partial traces as small Grams of V -----------
        if (wid == 0) {
            #pragma unroll
            for (int e = 0; e < 2; ++e) {
                const int idx = 2*lane + e;
                const int p = idx >> 3, q = idx & 7;
                float2 a = make_float2(0.f, 0.f);
                float2 d = make_float2(0.f, 0.f);
                #pragma unroll
                for (int m = 0; m < 2; ++m)
                    #pragma unroll
                    for (int c = 0; c < 4; ++c) {
                        a = cadd(a, cmulc(Vs[0][2*p+m][c], Vs[0][2*q+m][c]));
                        d = cadd(d, cmulc(Vs[0][p+8*m][c], Vs[0][q+8*m][c]));
                    }
                rho012[idx] = a;   // trace qubit 3 (LSB)
                rho123[idx] = d;   // trace qubit 0 (MSB)
            }
            if (lane < 16) {
                const int aa = lane >> 2, bb = lane & 3;
                float2 acc = make_float2(0.f, 0.f);
                #pragma unroll
                for (int xx = 0; xx < 4; ++xx)
                    #pragma unroll
                    for (int c = 0; c < 4; ++c)
                        acc = cadd(acc, cmulc(Vs[0][4*aa+xx][c], Vs[0][4*bb+xx][c]));
                rho01[lane] = acc;
            } else {
                const int v = lane - 16, aa = v >> 2, bb = v & 3;
                float2 acc = make_float2(0.f, 0.f);
                #pragma unroll
                for (int xx = 0; xx < 4; ++xx)
                    #pragma unroll
                    for (int c = 0; c < 4; ++c)
                        acc = cadd(acc, cmulc(Vs[0][4*xx+aa][c], Vs[0][4*xx+bb][c]));
                rho23[v] = acc;
            }
        } else if (wid == 1) {
            if (lane < 4) {
                const int p = lane >> 1, q = lane & 1;
                float2 acc = make_float2(0.f, 0.f);
                #pragma unroll
                for (int xx = 0; xx < 8; ++xx)
                    #pragma unroll
                    for (int c = 0; c < 4; ++c)
                        acc = cadd(acc, cmulc(Vs[1][8*p+xx][c], Vs[1][8*q+xx][c]));
                rq0[lane] = acc;   // block 1, keep qubit 0
            }
        } else {
            if (lane < 4) {
                const int p = lane >> 1, q = lane & 1;
                float2 acc = make_float2(0.f, 0.f);
                #pragma unroll
                for (int xx = 0; xx < 8; ++xx)
                    #pragma unroll
                    for (int c = 0; c < 4; ++c)
                        acc = cadd(acc, cmulc(Vs[2][2*xx+p][c], Vs[2][2*xx+q][c]));
                rq3[lane] = acc;   // block 3, keep qubit 3
            }
        }
    }
    __syncthreads();                                            // B1

    // ---------- Phase 3: Heisenberg expectation values (warp = kk) --------
    {
        const int kk = wid;
        float contrib = 0.f;
        #pragma unroll
        for (int e = 0; e < 2; ++e) {
            const int idx = 2*lane + e;
            const int oi = idx >> 3, oj = idx & 7;
            float2 val = make_float2(0.f, 0.f);
            #pragma unroll
            for (int pp = 0; pp < 2; ++pp) {
                const int p = pp ? (oi ^ 2) : oi;
                const float2 cA = pp ? make_float2(0.f, -s1v) : make_float2(c1, 0.f);
                #pragma unroll
                for (int qq = 0; qq < 2; ++qq) {
                    const int q = qq ? (p ^ 6) : p;
                    const float2 cB = qq ? make_float2(0.f, -s2v) : make_float2(c2, 0.f);
                    float2 cC;
                    if (q == oj)            cC = make_float2(c3, 0.f);
                    else if (q == (oj ^ 3)) cC = make_float2(0.f, -s3v);
                    else continue;
                    val = cadd(val, cmul(cmul(cA, cB), cC));
                }
            }
            const float dsign = ((oi >> 1) & 1) ? -1.f : 1.f;
            // rho[oj*8 + oi], with rk0/rk3 Kronecker products inlined
            float2 r;
            if      (kk == 0) r = cmul(rq3[(oj>>2)*2 + (oi>>2)],
                                       rho01[(oj&3)*4 + (oi&3)]);
            else if (kk == 1) r = rho012[oj*8 + oi];
            else if (kk == 2) r = rho123[oj*8 + oi];
            else              r = cmul(rho23[(oj>>1)*4 + (oi>>1)],
                                       rq0[(oj&1)*2 + (oi&1)]);
            contrib += dsign*(val.x*r.x - val.y*r.y);   // Re(O[i,j]*rho[j,i])
        }
        #pragma unroll
        for (int off = 16; off; off >>= 1)
            contrib += __shfl_down_sync(0xffffffffu, contrib, off);
        if (lane == 0) evals[kk] = contrib;
    }
    __syncthreads();                                            // B2

    // ---------- Phase 4: head + L2 normalize ------------------------------
    const float e0 = evals[0], e1 = evals[1], e2 = evals[2], e3 = evals[3];
    const float v0 = hb0 + e0*hwv0.x + e1*hwv0.y + e2*hwv0.z + e3*hwv0.w;
    const float v1 = hb1 + e0*hwv1.x + e1*hwv1.y + e2*hwv1.z + e3*hwv1.w;
    const float v2 = hb2 + e0*hwv2.x + e1*hwv2.y + e2*hwv2.z + e3*hwv2.w;
    const float v3 = hb3 + e0*hwv3.x + e1*hwv3.y + e2*hwv3.z + e3*hwv3.w;

    float sq = v0*v0 + v1*v1 + v2*v2 + v3*v3;
    #pragma unroll
    for (int off = 16; off; off >>= 1)
        sq += __shfl_down_sync(0xffffffffu, sq, off);
    if (lane == 0) rbuf[wid] = sq;
    __syncthreads();                                            // B3

    const float nrm = rbuf[0] + rbuf[1] + rbuf[2] + rbuf[3];
    const float scale = 1.f / fmaxf(sqrtf(nrm), 1e-12f);
    float* ob = out + (size_t)b*512;
    ob[t      ] = v0*scale;
    ob[t + 128] = v1*scale;
    ob[t + 256] = v2*scale;
    ob[t + 384] = v3*scale;
}

extern "C" void kernel_launch(void* const* d_in, const int* in_sizes, int n_in,
                              void* d_out, int out_size) {
    const float* x     = (const float*)d_in[0];   // (B,16,4,3)
    const float* pos_w = (const float*)d_in[1];   // (16,2)
    const float* l1    = (const float*)d_in[2];   // (20,2)
    const float* l2    = (const float*)d_in[3];   // (16,2)
    const float* hw    = (const float*)d_in[4];   // (512,4)
    const float* hb    = (const float*)d_in[5];   // (512,)
    float* out = (float*)d_out;

    const int B = in_sizes[0] / (16*4*3);
    iqp_embed_kernel<<<B, 128>>>(x, pos_w, l1, l2, hw, hb, out);
}

// round 5
// speedup vs baseline: 1.0333x; 1.0333x over previous
#include <cuda_runtime.h>
#include <math.h>

// QuantumIQPImageEmbedder — rank-4 factorized closed form, 256-thread shape.
//
// G = Psi Psi^H factorizes per qubit; absorbing single-qubit Ising phases
// into the kept states and expanding the two boundary couplings over the
// traced boundary-qubit values gives G = W W^H with W only 16x4.
// rho4 = (1/16)(H4 W)(H4 W)^H; every partial trace is a small Gram of
// V = (1/4) H4 W. The 16x16 Gram / WHTs are never materialized.
// Warps 0-2 own quantum blocks 0,1,3 end-to-end (syncwarp only);
// 3 block barriers total; 256 threads so the head/store tail is 2 rows/thread.

#define INV_SQRT2F 0.7071067811865476f

__device__ __forceinline__ float2 cmul(float2 a, float2 b) {
    return make_float2(a.x*b.x - a.y*b.y, a.x*b.y + a.y*b.x);
}
__device__ __forceinline__ float2 cmulc(float2 a, float2 b) { // a * conj(b)
    return make_float2(a.x*b.x + a.y*b.y, a.y*b.x - a.x*b.y);
}
__device__ __forceinline__ float2 cadd(float2 a, float2 b) {
    return make_float2(a.x + b.x, a.y + b.y);
}

__global__ void __launch_bounds__(256, 1)
iqp_embed_kernel(const float* __restrict__ x,        // (B,16,4,3)
                 const float* __restrict__ pos_w,    // (16,2)
                 const float* __restrict__ l1,       // (20,2)
                 const float* __restrict__ l2,       // (16,2)
                 const float* __restrict__ hw,       // (512,4)
                 const float* __restrict__ hb,       // (512,)
                 float* __restrict__ out)            // (B,512)
{
    const int b    = blockIdx.x;
    const int t    = threadIdx.x;       // 256 threads
    const int wid  = t >> 5;            // warp 0..7
    const int lane = t & 31;

    __shared__ float2 sprime[3][4][2];  // a-phase-absorbed kept states
    __shared__ float  sqp[3][2][2];     // sqrt boundary probs [slot][4/19][m]
    __shared__ float2 Vs[3][16][4];     // V = (1/4) H4 W per slot
    __shared__ float2 rho012[64], rho123[64], rho01[16], rho23[16];
    __shared__ float2 rq0[4], rq3[4];
    __shared__ float  evals[4], rbuf[8];

    // ---------- hoisted independent loads / trig (hidden under phase A) ----
    const float4 hwv0 = ((const float4*)hw)[t      ];
    const float4 hwv1 = ((const float4*)hw)[t + 256];
    const float  hb0 = hb[t], hb1 = hb[t + 256];

    // phase-3 trig: warp wid<4 handles expectation value kk = wid
    float c1, s1v, c2, s2v, c3, s3v;
    if (wid < 4) {
        __sincosf(l2[2*wid],                   &s1v, &c1);
        __sincosf(l2[2*((wid - 1) & 15) + 1],  &s2v, &c2);
        __sincosf(l2[2*wid + 1],               &s3v, &c3);
    }

    // ---------- Phases A/B/C: per-warp slot pipeline (warps 0-2) -----------
    if (wid < 3) {
        // phase-B trig (coupling factors)
        float cb0, sb0, cb1, sb1, cb2, sb2, cb3, sb3, cb19, sb19;
        __sincosf(0.5f*l1[1],  &sb0,  &cb0);   // b1[0]
        __sincosf(0.5f*l1[3],  &sb1,  &cb1);   // b1[1]
        __sincosf(0.5f*l1[5],  &sb2,  &cb2);   // b1[2]
        __sincosf(0.5f*l1[7],  &sb3,  &cb3);   // b1[3]  (boundary q3-q4)
        __sincosf(0.5f*l1[39], &sb19, &cb19);  // b1[19] (boundary q19-q0)

        const int kb = (wid == 2) ? 3 : wid;
        if (lane < 4) {
            // color qubit `lane` of patch 4*kb
            const float* xp = x + ((size_t)(b*16 + 4*kb)*4 + lane)*3;
            float cx, sx, cy, sy, cz, sz;
            __sincosf(0.5f*xp[0], &sx, &cx);
            __sincosf(0.5f*xp[1], &sy, &cy);
            __sincosf(0.5f*xp[2], &sz, &cz);
            float2 w0 = make_float2(cy*cx,  sy*sx);
            float2 w1 = make_float2(sy*cx, -cy*sx);
            float2 pz = make_float2(cz, -sz);
            w0 = cmul (w0, pz);
            w1 = cmulc(w1, pz);
            float2 s0 = make_float2((w0.x+w1.x)*INV_SQRT2F, (w0.y+w1.y)*INV_SQRT2F);
            float2 s1 = make_float2((w0.x-w1.x)*INV_SQRT2F, (w0.y-w1.y)*INV_SQRT2F);
            float sa, ca;  __sincosf(0.5f*l1[2*lane], &sa, &ca);   // a1[lane]
            sprime[wid][lane][0] = cmul(s0, make_float2(ca, -sa)); // z=+1
            sprime[wid][lane][1] = cmul(s1, make_float2(ca,  sa)); // z=-1
        } else if (lane < 6) {
            // boundary ancillas: q4 = anc of patch 4kb, q19 = anc of patch 4kb+3
            const int p = 4*kb + ((lane == 4) ? 0 : 3);
            float cx, sx, cy, sy;
            __sincosf(0.5f*pos_w[2*p],     &sx, &cx);
            __sincosf(0.5f*pos_w[2*p + 1], &sy, &cy);
            float2 w0 = make_float2(cy*cx,  sy*sx);
            float2 w1 = make_float2(sy*cx, -cy*sx);
            float2 s0 = make_float2((w0.x+w1.x)*INV_SQRT2F, (w0.y+w1.y)*INV_SQRT2F);
            float2 s1 = make_float2((w0.x-w1.x)*INV_SQRT2F, (w0.y-w1.y)*INV_SQRT2F);
            sqp[wid][lane-4][0] = sqrtf(s0.x*s0.x + s0.y*s0.y);
            sqp[wid][lane-4][1] = sqrtf(s1.x*s1.x + s1.y*s1.y);
        }
        __syncwarp();

        // ---------- Phase B: W columns, shuffle-WHT, V to smem ------------
        const int i  = lane & 15;
        const int i0 = (i>>3)&1, i1 = (i>>2)&1, i2 = (i>>1)&1, i3 = i&1;

        float2 u = cmul(cmul(sprime[wid][0][i0], sprime[wid][1][i1]),
                        cmul(sprime[wid][2][i2], sprime[wid][3][i3]));
        const float g0 = (i0 == i1) ? sb0 : -sb0;
        const float g1 = (i1 == i2) ? sb1 : -sb1;
        const float g2 = (i2 == i3) ? sb2 : -sb2;
        u = cmul(u, make_float2(cb0, -g0));
        u = cmul(u, make_float2(cb1, -g1));
        u = cmul(u, make_float2(cb2, -g2));

        const float zi3 = 1.f - 2.f*i3, zi0 = 1.f - 2.f*i0;
        const float2 g40  = make_float2(sqp[wid][0][0]*cb3,  -sqp[wid][0][0]*zi3*sb3);
        const float2 g41  = make_float2(sqp[wid][0][1]*cb3,   sqp[wid][0][1]*zi3*sb3);
        const float2 g190 = make_float2(sqp[wid][1][0]*cb19, -sqp[wid][1][0]*zi0*sb19);
        const float2 g191 = make_float2(sqp[wid][1][1]*cb19,  sqp[wid][1][1]*zi0*sb19);

        const float2 t0 = cmul(u, g40), t1 = cmul(u, g41);
        float2 w[4];
        w[0] = cmul(t0, g190);  w[1] = cmul(t0, g191);
        w[2] = cmul(t1, g190);  w[3] = cmul(t1, g191);

        #pragma unroll
        for (int m = 1; m < 16; m <<= 1) {
            #pragma unroll
            for (int c = 0; c < 4; ++c) {
                const float px = __shfl_xor_sync(0xffffffffu, w[c].x, m);
                const float py = __shfl_xor_sync(0xffffffffu, w[c].y, m);
                if (i & m) { w[c].x = px - w[c].x; w[c].y = py - w[c].y; }
                else       { w[c].x += px;         w[c].y += py;         }
            }
        }
        if (lane < 16) {
            #pragma unroll
            for (int c = 0; c < 4; ++c)
                Vs[wid][i][c] = make_float2(w[c].x*0.25f, w[c].y*0.25f);
        }
        __syncwarp();

        // ---------- Phase C: partial traces as small Grams of V -----------
        if (wid == 0) {
            #pragma unroll
            for (int e = 0; e < 2; ++e) {
                const int idx = 2*lane + e;
                const int p = idx >> 3, q = idx & 7;
                float2 a = make_float2(0.f, 0.f);
                float2 d = make_float2(0.f, 0.f);
                #pragma unroll
                for (int m = 0; m < 2; ++m)
                    #pragma unroll
                    for (int c = 0; c < 4; ++c) {
                        a = cadd(a, cmulc(Vs[0][2*p+m][c], Vs[0][2*q+m][c]));
                        d = cadd(d, cmulc(Vs[0][p+8*m][c], Vs[0][q+8*m][c]));
                    }
                rho012[idx] = a;   // trace qubit 3 (LSB)
                rho123[idx] = d;   // trace qubit 0 (MSB)
            }
            if (lane < 16) {
                const int aa = lane >> 2, bb = lane & 3;
                float2 acc = make_float2(0.f, 0.f);
                #pragma unroll
                for (int xx = 0; xx < 4; ++xx)
                    #pragma unroll
                    for (int c = 0; c < 4; ++c)
                        acc = cadd(acc, cmulc(Vs[0][4*aa+xx][c], Vs[0][4*bb+xx][c]));
                rho01[lane] = acc;
            } else {
                const int v = lane - 16, aa = v >> 2, bb = v & 3;
                float2 acc = make_float2(0.f, 0.f);
                #pragma unroll
                for (int xx = 0; xx < 4; ++xx)
                    #pragma unroll
                    for (int c = 0; c < 4; ++c)
                        acc = cadd(acc, cmulc(Vs[0][4*xx+aa][c], Vs[0][4*xx+bb][c]));
                rho23[v] = acc;
            }
        } else if (wid == 1) {
            if (lane < 4) {
                const int p = lane >> 1, q = lane & 1;
                float2 acc = make_float2(0.f, 0.f);
                #pragma unroll
                for (int xx = 0; xx < 8; ++xx)
                    #pragma unroll
                    for (int c = 0; c < 4; ++c)
                        acc = cadd(acc, cmulc(Vs[1][8*p+xx][c], Vs[1][8*q+xx][c]));
                rq0[lane] = acc;   // block 1, keep qubit 0
            }
        } else {
            if (lane < 4) {
                const int p = lane >> 1, q = lane & 1;
                float2 acc = make_float2(0.f, 0.f);
                #pragma unroll
                for (int xx = 0; xx < 8; ++xx)
                    #pragma unroll
                    for (int c = 0; c < 4; ++c)
                        acc = cadd(acc, cmulc(Vs[2][2*xx+p][c], Vs[2][2*xx+q][c]));
                rq3[lane] = acc;   // block 3, keep qubit 3
            }
        }
    }
    __syncthreads();                                            // B1

    // ---------- Phase 3: Heisenberg expectation values (warps 0-3) --------
    if (wid < 4) {
        const int kk = wid;
        float contrib = 0.f;
        #pragma unroll
        for (int e = 0; e < 2; ++e) {
            const int idx = 2*lane + e;
            const int oi = idx >> 3, oj = idx & 7;
            float2 val = make_float2(0.f, 0.f);
            #pragma unroll
            for (int pp = 0; pp < 2; ++pp) {
                const int p = pp ? (oi ^ 2) : oi;
                const float2 cA = pp ? make_float2(0.f, -s1v) : make_float2(c1, 0.f);
                #pragma unroll
                for (int qq = 0; qq < 2; ++qq) {
                    const int q = qq ? (p ^ 6) : p;
                    const float2 cB = qq ? make_float2(0.f, -s2v) : make_float2(c2, 0.f);
                    float2 cC;
                    if (q == oj)            cC = make_float2(c3, 0.f);
                    else if (q == (oj ^ 3)) cC = make_float2(0.f, -s3v);
                    else continue;
                    val = cadd(val, cmul(cmul(cA, cB), cC));
                }
            }
            const float dsign = ((oi >> 1) & 1) ? -1.f : 1.f;
            // rho[oj*8 + oi], rk0/rk3 Kronecker products inlined
            float2 r;
            if      (kk == 0) r = cmul(rq3[(oj>>2)*2 + (oi>>2)],
                                       rho01[(oj&3)*4 + (oi&3)]);
            else if (kk == 1) r = rho012[oj*8 + oi];
            else if (kk == 2) r = rho123[oj*8 + oi];
            else              r = cmul(rho23[(oj>>1)*4 + (oi>>1)],
                                       rq0[(oj&1)*2 + (oi&1)]);
            contrib += dsign*(val.x*r.x - val.y*r.y);   // Re(O[i,j]*rho[j,i])
        }
        #pragma unroll
        for (int off = 16; off; off >>= 1)
            contrib += __shfl_down_sync(0xffffffffu, contrib, off);
        if (lane == 0) evals[kk] = contrib;
    }
    __syncthreads();                                            // B2

    // ---------- Phase 4: head + L2 normalize (2 rows/thread) --------------
    const float e0 = evals[0], e1 = evals[1], e2 = evals[2], e3 = evals[3];
    const float v0 = hb0 + e0*hwv0.x + e1*hwv0.y + e2*hwv0.z + e3*hwv0.w;
    const float v1 = hb1 + e0*hwv1.x + e1*hwv1.y + e2*hwv1.z + e3*hwv1.w;

    float sq = v0*v0 + v1*v1;
    #pragma unroll
    for (int off = 16; off; off >>= 1)
        sq += __shfl_down_sync(0xffffffffu, sq, off);
    if (lane == 0) rbuf[wid] = sq;
    __syncthreads();                                            // B3

    float nrm = 0.f;
    #pragma unroll
    for (int w = 0; w < 8; ++w) nrm += rbuf[w];
    const float scale = 1.f / fmaxf(sqrtf(nrm), 1e-12f);
    float* ob = out + (size_t)b*512;
    ob[t      ] = v0*scale;
    ob[t + 256] = v1*scale;
}

extern "C" void kernel_launch(void* const* d_in, const int* in_sizes, int n_in,
                              void* d_out, int out_size) {
    const float* x     = (const float*)d_in[0];   // (B,16,4,3)
    const float* pos_w = (const float*)d_in[1];   // (16,2)
    const float* l1    = (const float*)d_in[2];   // (20,2)
    const float* l2    = (const float*)d_in[3];   // (16,2)
    const float* hw    = (const float*)d_in[4];   // (512,4)
    const float* hb    = (const float*)d_in[5];   // (512,)
    float* out = (float*)d_out;

    const int B = in_sizes[0] / (16*4*3);
    iqp_embed_kernel<<<B, 256>>>(x, pos_w, l1, l2, hw, hb, out);
}